// round 1
// baseline (speedup 1.0000x reference)
#include <cuda_runtime.h>
#include <math.h>

// ---------------- device scratch (no allocations allowed) ----------------
__device__ float g_LinvT[32 * 64 * 64];  // [k][e][d] = Linv_k[d][e]
__device__ float g_t[32 * 64];           // t_k = Linv_k * centroid_k
__device__ float g_nhc[32];              // -0.5*(D*log2pi + logdet_k)
__device__ float g_part[4096];           // per-block partial sums

#define LOG2PI 1.8378770664093453f

// ---------------- prep: Cholesky, logdet, triangular inverse ----------------
// grid = 32 (one block per component), block = 64 threads (one per row)
__global__ void __launch_bounds__(64) prep_kernel(const float* __restrict__ cov,
                                                  const float* __restrict__ centroid)
{
    __shared__ float A[64][65];   // cov -> L (lower)
    __shared__ float Li[64][65];  // L^{-1}
    __shared__ float dlog[64];

    const int k = blockIdx.x;
    const int i = threadIdx.x;

    // load cov[k] row i
    #pragma unroll 4
    for (int j = 0; j < 64; ++j) A[i][j] = cov[k * 4096 + i * 64 + j];
    __syncthreads();

    // left-looking Cholesky, thread i handles row i
    for (int j = 0; j < 64; ++j) {
        float s = 0.f;
        if (i >= j) {
            s = A[i][j];
            for (int m = 0; m < j; ++m) s -= A[i][m] * A[j][m];
            if (i == j) A[j][j] = sqrtf(s);
        }
        __syncthreads();
        if (i > j) A[i][j] = s / A[j][j];
        __syncthreads();
    }

    dlog[i] = 2.f * logf(A[i][i]);
    __syncthreads();
    if (i == 0) {
        float ld = 0.f;
        for (int m = 0; m < 64; ++m) ld += dlog[m];
        g_nhc[k] = -0.5f * (64.f * LOG2PI + ld);
    }

    // invert lower-triangular L: thread c = i solves L y = e_c (column c)
    {
        const int c = i;
        for (int r = 0; r < 64; ++r) {
            float v = 0.f;
            if (r >= c) {
                v = (r == c) ? 1.f : 0.f;
                for (int m = c; m < r; ++m) v -= A[r][m] * Li[m][c];
                v /= A[r][r];
            }
            Li[r][c] = v;   // zero above diagonal
        }
    }
    __syncthreads();

    // t_k[i] = sum_e Linv[i][e] * centroid[k][e]
    float tv = 0.f;
    for (int e = 0; e <= i; ++e) tv += Li[i][e] * centroid[k * 64 + e];
    g_t[k * 64 + i] = tv;

    // store transposed: g_LinvT[k][e][d] = Li[d][e]   (thread i = d, coalesced over d)
    #pragma unroll 4
    for (int e = 0; e < 64; ++e)
        g_LinvT[k * 4096 + e * 64 + i] = Li[i][e];
}

// ---------------- main: per-tile weighted quad accumulation ----------------
// grid = B/64, block = 128 threads
__global__ void __launch_bounds__(128) main_kernel(const float* __restrict__ emb,
                                                   const float* __restrict__ pi,
                                                   const int* __restrict__ labels)
{
    __shared__ float Xs[64][65];   // [e][b]  (padded: scattered writes)
    __shared__ float Ls[64][64];   // [e][d] = Linv[d][e]
    __shared__ float Ps[64][33];   // [b][k]  (padded)
    __shared__ float ts[64];
    __shared__ float nhc[32];
    __shared__ int   lbl[64];
    __shared__ float red[128];

    const int tid = threadIdx.x;
    const int b0  = blockIdx.x * 64;

    if (tid < 64) lbl[tid] = labels[b0 + tid];
    if (tid < 32) nhc[tid] = g_nhc[tid];
    __syncthreads();

    // gather embedding rows (transposed into Xs): e4 = tid%16, bsub = tid/16
    {
        const int e4 = tid & 15, bs = tid >> 4;
        #pragma unroll
        for (int it = 0; it < 8; ++it) {
            const int b = bs + it * 8;
            const float4 v = *(const float4*)(emb + (size_t)lbl[b] * 64 + e4 * 4);
            Xs[e4 * 4 + 0][b] = v.x;
            Xs[e4 * 4 + 1][b] = v.y;
            Xs[e4 * 4 + 2][b] = v.z;
            Xs[e4 * 4 + 3][b] = v.w;
        }
    }
    // gather pi rows: c4 = tid%8, bsub = tid/8
    {
        const int c4 = tid & 7, bs = tid >> 3;
        #pragma unroll
        for (int it = 0; it < 4; ++it) {
            const int b = bs + it * 16;
            const float4 v = *(const float4*)(pi + (size_t)lbl[b] * 32 + c4 * 4);
            Ps[b][c4 * 4 + 0] = v.x;
            Ps[b][c4 * 4 + 1] = v.y;
            Ps[b][c4 * 4 + 2] = v.z;
            Ps[b][c4 * 4 + 3] = v.w;
        }
    }

    const int w    = tid >> 5;          // warp 0..3
    const int lane = tid & 31;
    const int dx   = lane & 3;
    const int by   = lane >> 2;
    // permute d-range ownership per block so SMSPs get balanced triangular work
    const int w_eff = (w + (int)blockIdx.x) & 3;
    const int d0    = w_eff * 16 + dx * 4;
    const int e_end = w_eff * 16 + 16;  // Linv is lower-tri: z_d needs e <= d only

    float acc = 0.f;

    for (int k = 0; k < 32; ++k) {
        __syncthreads();  // protect Ls/ts reuse (also covers Xs/Ps writes on k==0)
        {
            const float4* src = (const float4*)(g_LinvT + k * 4096);
            float4*       dst = (float4*)(&Ls[0][0]);
            #pragma unroll
            for (int i = tid; i < 1024; i += 128) dst[i] = src[i];
            if (tid < 64) ts[tid] = g_t[k * 64 + tid];
        }
        __syncthreads();

        const float t0 = ts[d0], t1 = ts[d0 + 1], t2 = ts[d0 + 2], t3 = ts[d0 + 3];
        float z0[8], z1[8], z2[8], z3[8];
        #pragma unroll
        for (int i = 0; i < 8; ++i) { z0[i] = -t0; z1[i] = -t1; z2[i] = -t2; z3[i] = -t3; }

        #pragma unroll 4
        for (int e = 0; e < e_end; ++e) {
            const float l0 = Ls[e][d0];
            const float l1 = Ls[e][d0 + 1];
            const float l2 = Ls[e][d0 + 2];
            const float l3 = Ls[e][d0 + 3];
            #pragma unroll
            for (int i = 0; i < 8; ++i) {
                const float x = Xs[e][i * 8 + by];
                z0[i] = fmaf(x, l0, z0[i]);
                z1[i] = fmaf(x, l1, z1[i]);
                z2[i] = fmaf(x, l2, z2[i]);
                z3[i] = fmaf(x, l3, z3[i]);
            }
        }

        #pragma unroll
        for (int i = 0; i < 8; ++i) {
            const int b = i * 8 + by;
            float q = z0[i] * z0[i];
            q = fmaf(z1[i], z1[i], q);
            q = fmaf(z2[i], z2[i], q);
            q = fmaf(z3[i], z3[i], q);
            acc = fmaf(Ps[b][k], q, acc);   // partial quad (over this thread's 4 d's)
        }
    }
    acc *= -0.5f;

    // constant + logdet part: sum_k Ps[b][k] * nhc[k], one thread per b
    if (tid < 64) {
        float c = 0.f;
        #pragma unroll
        for (int k = 0; k < 32; ++k) c = fmaf(Ps[tid][k], nhc[k], c);
        acc += c;
    }

    // deterministic block reduction
    red[tid] = acc;
    __syncthreads();
    #pragma unroll
    for (int st = 64; st > 0; st >>= 1) {
        if (tid < st) red[tid] += red[tid + st];
        __syncthreads();
    }
    if (tid == 0) g_part[blockIdx.x] = red[0];
}

// ---------------- final reduce ----------------
__global__ void __launch_bounds__(1024) reduce_kernel(float* __restrict__ out, int nb)
{
    __shared__ float s[1024];
    const int t = threadIdx.x;
    float a = 0.f;
    for (int i = t; i < nb; i += 1024) a += g_part[i];
    s[t] = a;
    __syncthreads();
    #pragma unroll
    for (int st = 512; st > 0; st >>= 1) {
        if (t < st) s[t] += s[t + st];
        __syncthreads();
    }
    if (t == 0) out[0] = fabsf(s[0]);
}

// ---------------- launch ----------------
extern "C" void kernel_launch(void* const* d_in, const int* in_sizes, int n_in,
                              void* d_out, int out_size)
{
    const float* emb    = (const float*)d_in[0];   // (500000, 64)
    const float* cen    = (const float*)d_in[1];   // (32, 64)
    const float* cov    = (const float*)d_in[2];   // (32, 64, 64)
    const float* pi     = (const float*)d_in[3];   // (500000, 32)
    const int*   labels = (const int*)d_in[4];     // (B,)
    const int B  = in_sizes[4];
    const int nb = B / 64;

    prep_kernel<<<32, 64>>>(cov, cen);
    main_kernel<<<nb, 128>>>(emb, pi, labels);
    reduce_kernel<<<1, 1024>>>((float*)d_out, nb);
}